// round 2
// baseline (speedup 1.0000x reference)
#include <cuda_runtime.h>
#include <stdint.h>

// Problem-shape maxima (reference: N_SRC=100000, E=1250000, n_dst=50000)
#define MAX_SRC 100000
#define MAX_DST 50000
#define MAX_E   1250000

// Scratch (no device allocation allowed — __device__ globals)
__device__ int   g_deg_out[MAX_SRC];
__device__ int   g_deg_in[MAX_DST];
__device__ float g_norm_src[MAX_SRC];
__device__ int   g_off[MAX_DST + 1];
__device__ int   g_cursor[MAX_DST];
__device__ int   g_src_sorted[MAX_E];

// ---------------------------------------------------------------------------
// 1) zero the degree counters (must happen every call — graph replays)
__global__ void k_zero(int n_src, int n_dst) {
    int i = blockIdx.x * blockDim.x + threadIdx.x;
    if (i < n_src) g_deg_out[i] = 0;
    if (i < n_dst) g_deg_in[i] = 0;
}

// 2) degree counting: 2.5M spread int atomics
__global__ void k_count(const int* __restrict__ esrc,
                        const int* __restrict__ edst, int E) {
    int i = blockIdx.x * blockDim.x + threadIdx.x;
    if (i < E) {
        atomicAdd(&g_deg_out[esrc[i]], 1);
        atomicAdd(&g_deg_in[edst[i]], 1);
    }
}

// 3) single-block exclusive scan over in-degrees -> offsets; init cursors;
//    compute norm_src.
__global__ void k_scan(int n_src, int n_dst) {
    __shared__ int partial[1024];
    int tid = threadIdx.x;
    int C = (n_dst + 1023) / 1024;
    int beg = tid * C;
    int end = min(beg + C, n_dst);
    if (beg > n_dst) beg = n_dst;
    if (end < beg) end = beg;

    int s = 0;
    for (int i = beg; i < end; i++) s += g_deg_in[i];
    partial[tid] = s;
    __syncthreads();

    if (tid == 0) {
        int run = 0;
        for (int t = 0; t < 1024; t++) { int v = partial[t]; partial[t] = run; run += v; }
    }
    __syncthreads();

    int run = partial[tid];
    for (int i = beg; i < end; i++) {
        int v = g_deg_in[i];
        g_off[i] = run;
        g_cursor[i] = run;
        run += v;
    }
    if (end == n_dst) g_off[n_dst] = run;  // last owning thread writes the total

    for (int i = tid; i < n_src; i += 1024) {
        g_norm_src[i] = rsqrtf(fmaxf((float)g_deg_out[i], 1.0f));
    }
}

// 4) bucket edges by destination: 1.25M int atomics + scattered int stores
__global__ void k_bucket(const int* __restrict__ esrc,
                         const int* __restrict__ edst, int E) {
    int i = blockIdx.x * blockDim.x + threadIdx.x;
    if (i < E) {
        int d = edst[i];
        int pos = atomicAdd(&g_cursor[d], 1);
        g_src_sorted[pos] = esrc[i];
    }
}

// 5) gather: one warp per dst row. Lane l accumulates cols {2l, 2l+1} (float2).
//    Each edge = one coalesced 256B feat-row read, scaled by norm_src.
__global__ void k_gather(const float* __restrict__ feat,
                         float* __restrict__ out, int n_dst) {
    int warp = (blockIdx.x * blockDim.x + threadIdx.x) >> 5;
    int lane = threadIdx.x & 31;
    if (warp >= n_dst) return;

    int beg = g_off[warp];
    int end = g_off[warp + 1];

    const float2* __restrict__ feat2 = (const float2*)feat;

    float2 acc = make_float2(0.0f, 0.0f);

    int j = beg;
    // 4-way unroll for memory-level parallelism
    for (; j + 4 <= end; j += 4) {
        int s0 = g_src_sorted[j + 0];
        int s1 = g_src_sorted[j + 1];
        int s2 = g_src_sorted[j + 2];
        int s3 = g_src_sorted[j + 3];
        float n0 = g_norm_src[s0];
        float n1 = g_norm_src[s1];
        float n2 = g_norm_src[s2];
        float n3 = g_norm_src[s3];
        float2 v0 = feat2[s0 * 32 + lane];
        float2 v1 = feat2[s1 * 32 + lane];
        float2 v2 = feat2[s2 * 32 + lane];
        float2 v3 = feat2[s3 * 32 + lane];
        acc.x += v0.x * n0; acc.y += v0.y * n0;
        acc.x += v1.x * n1; acc.y += v1.y * n1;
        acc.x += v2.x * n2; acc.y += v2.y * n2;
        acc.x += v3.x * n3; acc.y += v3.y * n3;
    }
    for (; j < end; j++) {
        int s = g_src_sorted[j];
        float n = g_norm_src[s];
        float2 v = feat2[s * 32 + lane];
        acc.x += v.x * n; acc.y += v.y * n;
    }

    float nd = rsqrtf(fmaxf((float)g_deg_in[warp], 1.0f));
    ((float2*)out)[warp * 32 + lane] = make_float2(acc.x * nd, acc.y * nd);
}

// ---------------------------------------------------------------------------
extern "C" void kernel_launch(void* const* d_in, const int* in_sizes, int n_in,
                              void* d_out, int out_size) {
    const float* feat = (const float*)d_in[0];
    const int*   esrc = (const int*)d_in[1];
    const int*   edst = (const int*)d_in[2];
    float* out = (float*)d_out;

    int n_src = in_sizes[0] / 64;
    int E     = in_sizes[1];
    int n_dst = out_size / 64;

    int nz = (n_src > n_dst) ? n_src : n_dst;
    k_zero<<<(nz + 255) / 256, 256>>>(n_src, n_dst);
    k_count<<<(E + 255) / 256, 256>>>(esrc, edst, E);
    k_scan<<<1, 1024>>>(n_src, n_dst);
    k_bucket<<<(E + 255) / 256, 256>>>(esrc, edst, E);
    int threads = n_dst * 32;
    k_gather<<<(threads + 255) / 256, 256>>>(feat, out, n_dst);
}

// round 3
// speedup vs baseline: 1.2014x; 1.2014x over previous
#include <cuda_runtime.h>
#include <stdint.h>

// Problem-shape maxima (reference: N_SRC=100000, E=1250000, n_dst=50000)
#define MAX_SRC 100000
#define MAX_DST 50000
#define MAX_E   1250000

// Scratch (no device allocation allowed — __device__ globals)
__device__ int   g_deg_out[MAX_SRC];
__device__ int   g_deg_in[MAX_DST];
__device__ float g_norm_src[MAX_SRC];
__device__ int   g_off[MAX_DST + 1];
__device__ int   g_cursor[MAX_DST];
__device__ int   g_src_sorted[MAX_E];

// ---------------------------------------------------------------------------
// 1) zero the degree counters (every call — graph replays)
__global__ void k_zero(int n_src, int n_dst) {
    int i = blockIdx.x * blockDim.x + threadIdx.x;
    if (i < n_src) g_deg_out[i] = 0;
    if (i < n_dst) g_deg_in[i] = 0;
}

// 2) degree counting: 4 edges per thread via int4 loads; 2.5M spread int atomics
__global__ void k_count(const int4* __restrict__ esrc4,
                        const int4* __restrict__ edst4, int E4, int E,
                        const int* __restrict__ esrc,
                        const int* __restrict__ edst) {
    int i = blockIdx.x * blockDim.x + threadIdx.x;
    if (i < E4) {
        int4 s = esrc4[i];
        int4 d = edst4[i];
        atomicAdd(&g_deg_out[s.x], 1);
        atomicAdd(&g_deg_out[s.y], 1);
        atomicAdd(&g_deg_out[s.z], 1);
        atomicAdd(&g_deg_out[s.w], 1);
        atomicAdd(&g_deg_in[d.x], 1);
        atomicAdd(&g_deg_in[d.y], 1);
        atomicAdd(&g_deg_in[d.z], 1);
        atomicAdd(&g_deg_in[d.w], 1);
    }
    // tail (E not multiple of 4)
    int t = E4 * 4 + i;
    if (i < (E - E4 * 4)) {
        atomicAdd(&g_deg_out[esrc[t]], 1);
        atomicAdd(&g_deg_in[edst[t]], 1);
    }
}

// 3) single-block exclusive scan over in-degrees -> offsets; init cursors.
//    Parallel scan of the 1024 per-thread partials (warp shuffles).
__global__ void k_scan(int n_dst) {
    __shared__ int partial[1024];
    __shared__ int warp_sums[32];
    int tid  = threadIdx.x;
    int lane = tid & 31;
    int wid  = tid >> 5;

    int C = (n_dst + 1023) / 1024;
    int beg = min(tid * C, n_dst);
    int end = min(beg + C, n_dst);

    int s = 0;
    for (int i = beg; i < end; i++) s += g_deg_in[i];

    // inclusive warp scan
    int x = s;
    #pragma unroll
    for (int o = 1; o < 32; o <<= 1) {
        int y = __shfl_up_sync(0xFFFFFFFF, x, o);
        if (lane >= o) x += y;
    }
    if (lane == 31) warp_sums[wid] = x;
    __syncthreads();
    if (wid == 0) {
        int w = (lane < 32) ? warp_sums[lane] : 0;
        #pragma unroll
        for (int o = 1; o < 32; o <<= 1) {
            int y = __shfl_up_sync(0xFFFFFFFF, w, o);
            if (lane >= o) w += y;
        }
        warp_sums[lane] = w;  // inclusive
    }
    __syncthreads();

    int base = (x - s) + (wid > 0 ? warp_sums[wid - 1] : 0);  // exclusive prefix

    int run = base;
    for (int i = beg; i < end; i++) {
        int v = g_deg_in[i];
        g_off[i] = run;
        g_cursor[i] = run;
        run += v;
    }
    if (end == n_dst && beg <= n_dst) {
        if (tid == 1023 || end > beg || beg == n_dst) {
            // exactly one thread owns index n_dst: the one whose chunk ends there
            if (beg < n_dst || tid == 1023) g_off[n_dst] = run;
        }
    }
    // simpler guarantee: last thread recomputes total
    if (tid == 1023) {
        int total = warp_sums[31];
        g_off[n_dst] = total;
    }
}

// 4) bucket edges by destination (4 edges/thread) + compute norm_src
__global__ void k_bucket(const int4* __restrict__ esrc4,
                         const int4* __restrict__ edst4, int E4, int E,
                         const int* __restrict__ esrc,
                         const int* __restrict__ edst, int n_src) {
    int i = blockIdx.x * blockDim.x + threadIdx.x;
    if (i < E4) {
        int4 s = esrc4[i];
        int4 d = edst4[i];
        g_src_sorted[atomicAdd(&g_cursor[d.x], 1)] = s.x;
        g_src_sorted[atomicAdd(&g_cursor[d.y], 1)] = s.y;
        g_src_sorted[atomicAdd(&g_cursor[d.z], 1)] = s.z;
        g_src_sorted[atomicAdd(&g_cursor[d.w], 1)] = s.w;
    }
    int t = E4 * 4 + i;
    if (i < (E - E4 * 4)) {
        g_src_sorted[atomicAdd(&g_cursor[edst[t]], 1)] = esrc[t];
    }
    // norm_src (deg_out is final after k_count); grid covers E4 threads >= n_src
    if (i < n_src) {
        g_norm_src[i] = rsqrtf(fmaxf((float)g_deg_out[i], 1.0f));
    }
}

// 5) gather: one warp per dst row, lane l holds cols {2l,2l+1} (float2).
//    8-way unroll: 8 idx loads -> 8 norm loads -> 8 row loads in flight.
__global__ void k_gather(const float* __restrict__ feat,
                         float* __restrict__ out, int n_dst) {
    int warp = (blockIdx.x * blockDim.x + threadIdx.x) >> 5;
    int lane = threadIdx.x & 31;
    if (warp >= n_dst) return;

    int beg = g_off[warp];
    int end = g_off[warp + 1];

    const float2* __restrict__ feat2 = (const float2*)feat;

    float2 acc = make_float2(0.0f, 0.0f);

    int j = beg;
    for (; j + 8 <= end; j += 8) {
        int s0 = g_src_sorted[j + 0];
        int s1 = g_src_sorted[j + 1];
        int s2 = g_src_sorted[j + 2];
        int s3 = g_src_sorted[j + 3];
        int s4 = g_src_sorted[j + 4];
        int s5 = g_src_sorted[j + 5];
        int s6 = g_src_sorted[j + 6];
        int s7 = g_src_sorted[j + 7];
        float n0 = g_norm_src[s0];
        float n1 = g_norm_src[s1];
        float n2 = g_norm_src[s2];
        float n3 = g_norm_src[s3];
        float n4 = g_norm_src[s4];
        float n5 = g_norm_src[s5];
        float n6 = g_norm_src[s6];
        float n7 = g_norm_src[s7];
        float2 v0 = feat2[s0 * 32 + lane];
        float2 v1 = feat2[s1 * 32 + lane];
        float2 v2 = feat2[s2 * 32 + lane];
        float2 v3 = feat2[s3 * 32 + lane];
        float2 v4 = feat2[s4 * 32 + lane];
        float2 v5 = feat2[s5 * 32 + lane];
        float2 v6 = feat2[s6 * 32 + lane];
        float2 v7 = feat2[s7 * 32 + lane];
        acc.x += v0.x * n0; acc.y += v0.y * n0;
        acc.x += v1.x * n1; acc.y += v1.y * n1;
        acc.x += v2.x * n2; acc.y += v2.y * n2;
        acc.x += v3.x * n3; acc.y += v3.y * n3;
        acc.x += v4.x * n4; acc.y += v4.y * n4;
        acc.x += v5.x * n5; acc.y += v5.y * n5;
        acc.x += v6.x * n6; acc.y += v6.y * n6;
        acc.x += v7.x * n7; acc.y += v7.y * n7;
    }
    for (; j < end; j++) {
        int s = g_src_sorted[j];
        float n = g_norm_src[s];
        float2 v = feat2[s * 32 + lane];
        acc.x += v.x * n; acc.y += v.y * n;
    }

    float nd = rsqrtf(fmaxf((float)(end - beg), 1.0f));
    ((float2*)out)[warp * 32 + lane] = make_float2(acc.x * nd, acc.y * nd);
}

// ---------------------------------------------------------------------------
extern "C" void kernel_launch(void* const* d_in, const int* in_sizes, int n_in,
                              void* d_out, int out_size) {
    const float* feat = (const float*)d_in[0];
    const int*   esrc = (const int*)d_in[1];
    const int*   edst = (const int*)d_in[2];
    float* out = (float*)d_out;

    int n_src = in_sizes[0] / 64;
    int E     = in_sizes[1];
    int n_dst = out_size / 64;

    int E4 = E / 4;
    const int4* esrc4 = (const int4*)esrc;
    const int4* edst4 = (const int4*)edst;

    int nz = (n_src > n_dst) ? n_src : n_dst;
    k_zero<<<(nz + 255) / 256, 256>>>(n_src, n_dst);
    k_count<<<(E4 + 255) / 256, 256>>>(esrc4, edst4, E4, E, esrc, edst);
    k_scan<<<1, 1024>>>(n_dst);
    // grid must cover both E4 edge-quads and n_src norm computations
    int nb = ((E4 > n_src ? E4 : n_src) + 255) / 256;
    k_bucket<<<nb, 256>>>(esrc4, edst4, E4, E, esrc, edst, n_src);
    int threads = n_dst * 32;
    k_gather<<<(threads + 255) / 256, 256>>>(feat, out, n_dst);
}